// round 8
// baseline (speedup 1.0000x reference)
#include <cuda_runtime.h>
#include <math.h>

#define BB 16
#define NN 16384
#define TOTAL (BB * NN)
#define NCHUNK (NN / 32)        // 512
#define NGROUP (NCHUNK / 4)     // 128 groups of 4 chunks

// Scratch (padded so tail prefetches stay in-bounds; pad values never used).
__device__ float4 g_cA[TOTAL + 512];
__device__ float4 g_cB[TOTAL + 512];
__device__ int    g_mt[TOTAL + 512];

// ---------------------------------------------------------------------------
// Pass 1: fully parallel coefficient computation.
//   blk[0]=b0*w0; blk[j]=b0*w[j]+a1*w[j-1] (j=1..5); blk[6]=a1*w5;  B.w=x[n].
//   meta = lo | (mm<<8) | (r<<16):
//     lo = (base-6)&255   ring slot of window start (base = n - zc)
//     mm = (n&31) - zc + 97   (tap j is in chunk c-1  <=>  mm >= 65+j)
//     r  = base & 31          shuffle lane for tap 0
// ---------------------------------------------------------------------------
__global__ void __launch_bounds__(256)
coef_kernel(const float* __restrict__ f0,
            const float* __restrict__ x,
            const float* __restrict__ lb)
{
    int i = blockIdx.x * blockDim.x + threadIdx.x;
    if (i >= TOTAL) return;
    int n = i & (NN - 1);

    float2 gp = reinterpret_cast<const float2*>(lb)[i];
    float g  = 0.99f * gp.x;
    float p  = gp.y;
    float b0 = g * (1.0f - p);
    float a1 = g * p;
    float f0c = f0[i] - a1 / (b0 + a1 + 1e-7f);

    int   zc    = (int)floorf(f0c) - 2;     // in [37, 97]
    float alpha = f0c - (float)zc;          // in [2, 3)

    float u0 = alpha;
    float u1 = alpha - 1.0f;
    float u2 = alpha - 2.0f;
    float u3 = alpha - 3.0f;
    float u4 = alpha - 4.0f;
    float u5 = alpha - 5.0f;

    float pre1 = u0;
    float pre2 = pre1 * u1;
    float pre3 = pre2 * u2;
    float pre4 = pre3 * u3;
    float pre5 = pre4 * u4;
    float suf4 = u5;
    float suf3 = suf4 * u4;
    float suf2 = suf3 * u3;
    float suf1 = suf2 * u2;
    float suf0 = suf1 * u1;

    float w0 = suf0        * (-1.0f / 120.0f);
    float w1 = pre1 * suf1 * ( 1.0f /  24.0f);
    float w2 = pre2 * suf2 * (-1.0f /  12.0f);
    float w3 = pre3 * suf3 * ( 1.0f /  12.0f);
    float w4 = pre4 * suf4 * (-1.0f /  24.0f);
    float w5 = pre5        * ( 1.0f / 120.0f);

    g_cA[i] = make_float4(b0 * w0,
                          fmaf(b0, w1, a1 * w0),
                          fmaf(b0, w2, a1 * w1),
                          fmaf(b0, w3, a1 * w2));
    g_cB[i] = make_float4(fmaf(b0, w4, a1 * w3),
                          fmaf(b0, w5, a1 * w4),
                          a1 * w5,
                          x[i]);
    int base = n - zc;
    int lo   = (base - 6) & 255;
    int mm   = (n & 31) - zc + 97;          // in [0, 91]
    int r    = base & 31;
    g_mt[i] = lo | (mm << 8) | (r << 16);
}

// ---------------------------------------------------------------------------
// cp.async helpers
// ---------------------------------------------------------------------------
__device__ __forceinline__ void cp16(void* dst, const void* src) {
    unsigned int d = (unsigned int)__cvta_generic_to_shared(dst);
    asm volatile("cp.async.ca.shared.global [%0], [%1], 16;" :: "r"(d), "l"(src));
}
__device__ __forceinline__ void cp4(void* dst, const void* src) {
    unsigned int d = (unsigned int)__cvta_generic_to_shared(dst);
    asm volatile("cp.async.ca.shared.global [%0], [%1], 4;" :: "r"(d), "l"(src));
}
__device__ __forceinline__ void cp_commit() {
    asm volatile("cp.async.commit_group;");
}
__device__ __forceinline__ void cp_wait2() {
    asm volatile("cp.async.wait_group 2;");
}

// ---------------------------------------------------------------------------
// Pass 2: sequential recurrence. One block = 2 warps per batch row.
//   warp 0 (compute): y[n] = x[n] + sum_j blk[j]*y[base-j], delays in [37,103].
//     Chunks processed in pairs with ONE __syncwarp per pair:
//       - pair-start sync publishes ring STS through chunk even-1
//       - even chunk: all 7 taps from the ring
//       - odd  chunk: taps from chunk c-1 via __shfl_sync of the even acc
//         (dest-side predicate mm >= 65+j); older taps from the ring, whose
//         LDS issue right after the pair sync (off the serial chain). Stale
//         ring reads under selected-out taps are discarded.
//     Ring: 256 + 7-slot mirror, pre-zeroed => zero initial state free.
//     Group's 12 coefficient LDS batched into registers after the group bar.
//   warp 1 (helper): streams coefficients gmem->SMEM via cp.async (16-stage,
//     3-group lead); one __syncthreads per 4-chunk group publishes the next
//     group and drains compute's STS for the group boundary.
// ---------------------------------------------------------------------------
struct SmemCoef {
    float4 A[16][32];
    float4 B[16][32];
    int    I[16][32];
};

__device__ __forceinline__ void prefetch_chunk(SmemCoef* s, int st, int c, int lane,
                                               const float4* cA, const float4* cB,
                                               const int* cI)
{
    int idx = c * 32 + lane;
    cp16(&s->A[st][lane], cA + idx);
    cp16(&s->B[st][lane], cB + idx);
    cp4 (&s->I[st][lane], cI + idx);
}

__device__ __forceinline__ float proc_even(float4 A, float4 B, int meta,
                                           float* ring, int wslot, int lane,
                                           bool mirror, float* op)
{
    const int lo = meta & 255;
    const float* w = ring + lo;              // window [lo, lo+6], never wraps
    float v6 = w[0];
    float v5 = w[1];
    float v4 = w[2];
    float v3 = w[3];
    float v2 = w[4];
    float v1 = w[5];
    float v0 = w[6];

    float t0 = fmaf(A.x, v0, B.w);           // x[n] + blk0*v0
    float t1 = fmaf(A.z, v2, A.y * v1);
    float t2 = fmaf(B.x, v4, A.w * v3);
    float t3 = fmaf(B.z, v6, B.y * v5);
    float acc = (t0 + t1) + (t2 + t3);

    ring[wslot + lane] = acc;
    if (mirror) ring[256 + lane] = acc;
    *op = acc;
    return acc;
}

__device__ __forceinline__ void proc_odd(float4 A, float4 B, int meta,
                                         float* ring, int wslot, int lane,
                                         float prev, float* op)
{
    const int lo = meta & 255;
    const int mm = (meta >> 8) & 255;
    const int r  = meta >> 16;

    const float* w = ring + lo;              // stale where shfl wins; discarded
    float g6 = w[0];
    float g5 = w[1];
    float g4 = w[2];
    float g3 = w[3];
    float g2 = w[4];
    float g1 = w[5];
    float g0 = w[6];

    float h0 = __shfl_sync(0xffffffffu, prev,  r          );
    float h1 = __shfl_sync(0xffffffffu, prev, (r - 1) & 31);
    float h2 = __shfl_sync(0xffffffffu, prev, (r - 2) & 31);
    float h3 = __shfl_sync(0xffffffffu, prev, (r - 3) & 31);
    float h4 = __shfl_sync(0xffffffffu, prev, (r - 4) & 31);
    float h5 = __shfl_sync(0xffffffffu, prev, (r - 5) & 31);
    float h6 = __shfl_sync(0xffffffffu, prev, (r - 6) & 31);

    float v0 = (mm >= 65) ? h0 : g0;
    float v1 = (mm >= 66) ? h1 : g1;
    float v2 = (mm >= 67) ? h2 : g2;
    float v3 = (mm >= 68) ? h3 : g3;
    float v4 = (mm >= 69) ? h4 : g4;
    float v5 = (mm >= 70) ? h5 : g5;
    float v6 = (mm >= 71) ? h6 : g6;

    float t0 = fmaf(A.x, v0, B.w);
    float t1 = fmaf(A.z, v2, A.y * v1);
    float t2 = fmaf(B.x, v4, A.w * v3);
    float t3 = fmaf(B.z, v6, B.y * v5);
    float acc = (t0 + t1) + (t2 + t3);

    ring[wslot + lane] = acc;
    *op = acc;
}

__global__ void __launch_bounds__(64, 1)
lpc_kernel(float* __restrict__ out)
{
    __shared__ SmemCoef sc;
    __shared__ float ring[264];

    const int b    = blockIdx.x;
    const int tid  = threadIdx.x;
    const int wid  = tid >> 5;
    const int lane = tid & 31;
    const float4* __restrict__ cA = g_cA + b * NN;
    const float4* __restrict__ cB = g_cB + b * NN;
    const int*    __restrict__ cI = g_mt + b * NN;

    if (wid == 0) {
        // zero the ring (implements zero initial state via wrap mapping)
#pragma unroll
        for (int k = 0; k < 8; k++) ring[lane + 32 * k] = 0.0f;
        if (lane < 8) ring[256 + lane] = 0.0f;
    } else {
        // prime pipeline: groups 0,1,2 -> stages 0-11
#pragma unroll
        for (int gp = 0; gp < 3; gp++) {
#pragma unroll
            for (int k = 0; k < 4; k++)
                prefetch_chunk(&sc, gp * 4 + k, gp * 4 + k, lane, cA, cB, cI);
            cp_commit();
        }
        cp_wait2();                     // group 0 resident
    }
    __syncthreads();

    if (wid == 0) {
        // ---------------- compute warp ----------------
        const bool lane_lt7 = lane < 7;
        float* __restrict__ op = out + b * NN + lane;

        for (int g = 0; g < NGROUP; g++) {
            const int st = (g & 3) * 4;
            const int wb = (g & 1) * 128;         // ring write base for group
            const bool mir = ((g & 1) == 0) && lane_lt7;  // chunk c%8==0

            // batch the group's coefficients into registers (12 LDS)
            float4 A0 = sc.A[st + 0][lane], B0 = sc.B[st + 0][lane];
            float4 A1 = sc.A[st + 1][lane], B1 = sc.B[st + 1][lane];
            float4 A2 = sc.A[st + 2][lane], B2 = sc.B[st + 2][lane];
            float4 A3 = sc.A[st + 3][lane], B3 = sc.B[st + 3][lane];
            int m0 = sc.I[st + 0][lane];
            int m1 = sc.I[st + 1][lane];
            int m2 = sc.I[st + 2][lane];
            int m3 = sc.I[st + 3][lane];

            float* opg = op + g * 128;

            // pair 0: chunks 4g (even), 4g+1 (odd) — ordered by group barrier
            float a0 = proc_even(A0, B0, m0, ring, wb,      lane, mir,  opg);
            proc_odd            (A1, B1, m1, ring, wb + 32, lane, a0,   opg + 32);

            __syncwarp();                          // publish chunks 4g, 4g+1

            // pair 1: chunks 4g+2 (even), 4g+3 (odd)
            float a2 = proc_even(A2, B2, m2, ring, wb + 64, lane, false, opg + 64);
            proc_odd            (A3, B3, m3, ring, wb + 96, lane, a2,    opg + 96);

            __syncthreads();                       // next group published
        }
    } else {
        // ---------------- helper warp ----------------
        for (int g = 0; g < NGROUP; g++) {
            const int pg = g + 3;                 // group to prefetch
            const int st = (pg & 3) * 4;
#pragma unroll
            for (int k = 0; k < 4; k++)
                prefetch_chunk(&sc, st + k, pg * 4 + k, lane, cA, cB, cI);
            cp_commit();
            cp_wait2();                           // group g+1 resident
            __syncthreads();
        }
    }
}

// ---------------------------------------------------------------------------
// Inputs (metadata order): f0 [B,N] f32, x [B,N] f32, l_b [B,N,2] f32, K int32
// Output: y [B,N] f32
// ---------------------------------------------------------------------------
extern "C" void kernel_launch(void* const* d_in, const int* in_sizes, int n_in,
                              void* d_out, int out_size)
{
    const float* f0 = (const float*)d_in[0];
    const float* x  = (const float*)d_in[1];
    const float* lb = (const float*)d_in[2];
    float* out = (float*)d_out;

    coef_kernel<<<TOTAL / 256, 256>>>(f0, x, lb);
    lpc_kernel<<<BB, 64>>>(out);
}

// round 9
// speedup vs baseline: 1.1136x; 1.1136x over previous
#include <cuda_runtime.h>
#include <math.h>

#define BB 16
#define NN 16384
#define TOTAL (BB * NN)
#define NCHUNK (NN / 32)        // 512
#define NGROUP (NCHUNK / 4)     // 128 groups of 4 chunks

// Scratch (padded so tail prefetches stay in-bounds; pad values never used).
__device__ float4 g_cA[TOTAL + 512];
__device__ float4 g_cB[TOTAL + 512];
__device__ int    g_lo[TOTAL + 512];

// ---------------------------------------------------------------------------
// Pass 1: fully parallel coefficient computation.
//   blk[0]=b0*w0; blk[j]=b0*w[j]+a1*w[j-1] (j=1..5); blk[6]=a1*w5;  B.w=x[n].
//   Stores lo = (n - zc - 6) & 255 (ring slot of the 7-tap window start).
// ---------------------------------------------------------------------------
__global__ void __launch_bounds__(256)
coef_kernel(const float* __restrict__ f0,
            const float* __restrict__ x,
            const float* __restrict__ lb)
{
    int i = blockIdx.x * blockDim.x + threadIdx.x;
    if (i >= TOTAL) return;
    int n = i & (NN - 1);

    float2 gp = reinterpret_cast<const float2*>(lb)[i];
    float g  = 0.99f * gp.x;
    float p  = gp.y;
    float b0 = g * (1.0f - p);
    float a1 = g * p;
    float f0c = f0[i] - a1 / (b0 + a1 + 1e-7f);

    int   zc    = (int)floorf(f0c) - 2;     // in [37, 97]
    float alpha = f0c - (float)zc;          // in [2, 3)

    float u0 = alpha;
    float u1 = alpha - 1.0f;
    float u2 = alpha - 2.0f;
    float u3 = alpha - 3.0f;
    float u4 = alpha - 4.0f;
    float u5 = alpha - 5.0f;

    float pre1 = u0;
    float pre2 = pre1 * u1;
    float pre3 = pre2 * u2;
    float pre4 = pre3 * u3;
    float pre5 = pre4 * u4;
    float suf4 = u5;
    float suf3 = suf4 * u4;
    float suf2 = suf3 * u3;
    float suf1 = suf2 * u2;
    float suf0 = suf1 * u1;

    float w0 = suf0        * (-1.0f / 120.0f);
    float w1 = pre1 * suf1 * ( 1.0f /  24.0f);
    float w2 = pre2 * suf2 * (-1.0f /  12.0f);
    float w3 = pre3 * suf3 * ( 1.0f /  12.0f);
    float w4 = pre4 * suf4 * (-1.0f /  24.0f);
    float w5 = pre5        * ( 1.0f / 120.0f);

    g_cA[i] = make_float4(b0 * w0,
                          fmaf(b0, w1, a1 * w0),
                          fmaf(b0, w2, a1 * w1),
                          fmaf(b0, w3, a1 * w2));
    g_cB[i] = make_float4(fmaf(b0, w4, a1 * w3),
                          fmaf(b0, w5, a1 * w4),
                          a1 * w5,
                          x[i]);
    g_lo[i] = (n - zc - 6) & 255;
}

// ---------------------------------------------------------------------------
// cp.async helpers
// ---------------------------------------------------------------------------
__device__ __forceinline__ void cp16(void* dst, const void* src) {
    unsigned int d = (unsigned int)__cvta_generic_to_shared(dst);
    asm volatile("cp.async.ca.shared.global [%0], [%1], 16;" :: "r"(d), "l"(src));
}
__device__ __forceinline__ void cp4(void* dst, const void* src) {
    unsigned int d = (unsigned int)__cvta_generic_to_shared(dst);
    asm volatile("cp.async.ca.shared.global [%0], [%1], 4;" :: "r"(d), "l"(src));
}
__device__ __forceinline__ void cp_commit() {
    asm volatile("cp.async.commit_group;");
}
__device__ __forceinline__ void cp_wait1() {
    asm volatile("cp.async.wait_group 1;");
}

// ---------------------------------------------------------------------------
// Pass 2: sequential recurrence. One block = 2 warps per batch row.
//   warp 0 (compute): y[n] = x[n] + sum_j blk[j]*y[n-zc-j], delays in [37,103].
//     Minimal loop: per chunk only 7 ring LDS + 8 FMA + ring STS + __syncwarp.
//     - group g+1's 12 coefficient LDS issue at the END of iteration g (after
//       last use of group g regs), so nothing but ring LDS follows the group
//       barrier on the critical path.
//     - output STG is NOT done here (helper copies ring->gmem).
//     Ring: 256 + 7-slot mirror, pre-zeroed => zero initial state free.
//   warp 1 (helper): per group: cp.async-prefetch group g+3 (16-stage buffer),
//     commit, wait_group 1 (=> group g+1 resident, published at this group's
//     barrier); copy group g-1's ring slots to gmem; __syncthreads.
//     Safety: group g-1's slots are overwritten only in group g+1, and the
//     group barriers order compute's STS before helper's LDS.
// ---------------------------------------------------------------------------
struct SmemCoef {
    float4 A[16][32];
    float4 B[16][32];
    int    I[16][32];
};

__device__ __forceinline__ void prefetch_chunk(SmemCoef* s, int st, int c, int lane,
                                               const float4* cA, const float4* cB,
                                               const int* cI)
{
    int idx = c * 32 + lane;
    cp16(&s->A[st][lane], cA + idx);
    cp16(&s->B[st][lane], cB + idx);
    cp4 (&s->I[st][lane], cI + idx);
}

__global__ void __launch_bounds__(64, 1)
lpc_kernel(float* __restrict__ out)
{
    __shared__ SmemCoef sc;
    __shared__ float ring[264];

    const int b    = blockIdx.x;
    const int tid  = threadIdx.x;
    const int wid  = tid >> 5;
    const int lane = tid & 31;
    const float4* __restrict__ cA = g_cA + b * NN;
    const float4* __restrict__ cB = g_cB + b * NN;
    const int*    __restrict__ cI = g_lo + b * NN;

    if (wid == 0) {
        // zero the ring (implements zero initial state via wrap mapping)
#pragma unroll
        for (int k = 0; k < 8; k++) ring[lane + 32 * k] = 0.0f;
        if (lane < 8) ring[256 + lane] = 0.0f;
    } else {
        // prime pipeline: groups 0,1,2 -> stages 0-11
#pragma unroll
        for (int gp = 0; gp < 3; gp++) {
#pragma unroll
            for (int k = 0; k < 4; k++)
                prefetch_chunk(&sc, gp * 4 + k, gp * 4 + k, lane, cA, cB, cI);
            cp_commit();
        }
        cp_wait1();                      // groups 0 and 1 resident
    }
    __syncthreads();

    if (wid == 0) {
        // ---------------- compute warp ----------------
        const bool lane_lt7 = lane < 7;

        // group 0 coefficients (resident; published by the barrier above)
        float4 A0 = sc.A[0][lane], B0 = sc.B[0][lane];
        float4 A1 = sc.A[1][lane], B1 = sc.B[1][lane];
        float4 A2 = sc.A[2][lane], B2 = sc.B[2][lane];
        float4 A3 = sc.A[3][lane], B3 = sc.B[3][lane];
        int l0 = sc.I[0][lane];
        int l1 = sc.I[1][lane];
        int l2 = sc.I[2][lane];
        int l3 = sc.I[3][lane];

        for (int g = 0; g < NGROUP; g++) {
            const int wb = (g & 1) * 128;           // ring write base
            const bool mir = ((g & 1) == 0) && lane_lt7;

            // ---- chunk 0 (ordered by the group barrier) ----
            {
                const float* w = ring + l0;
                float v6 = w[0], v5 = w[1], v4 = w[2], v3 = w[3];
                float v2 = w[4], v1 = w[5], v0 = w[6];
                float t0 = fmaf(A0.x, v0, B0.w);
                float t1 = fmaf(A0.z, v2, A0.y * v1);
                float t2 = fmaf(B0.x, v4, A0.w * v3);
                float t3 = fmaf(B0.z, v6, B0.y * v5);
                float acc = (t0 + t1) + (t2 + t3);
                ring[wb + lane] = acc;
                if (mir) ring[256 + lane] = acc;
            }
            __syncwarp();
            // ---- chunk 1 ----
            {
                const float* w = ring + l1;
                float v6 = w[0], v5 = w[1], v4 = w[2], v3 = w[3];
                float v2 = w[4], v1 = w[5], v0 = w[6];
                float t0 = fmaf(A1.x, v0, B1.w);
                float t1 = fmaf(A1.z, v2, A1.y * v1);
                float t2 = fmaf(B1.x, v4, A1.w * v3);
                float t3 = fmaf(B1.z, v6, B1.y * v5);
                ring[wb + 32 + lane] = (t0 + t1) + (t2 + t3);
            }
            __syncwarp();
            // ---- chunk 2 ----
            {
                const float* w = ring + l2;
                float v6 = w[0], v5 = w[1], v4 = w[2], v3 = w[3];
                float v2 = w[4], v1 = w[5], v0 = w[6];
                float t0 = fmaf(A2.x, v0, B2.w);
                float t1 = fmaf(A2.z, v2, A2.y * v1);
                float t2 = fmaf(B2.x, v4, A2.w * v3);
                float t3 = fmaf(B2.z, v6, B2.y * v5);
                ring[wb + 64 + lane] = (t0 + t1) + (t2 + t3);
            }
            __syncwarp();
            // ---- chunk 3 ----
            {
                const float* w = ring + l3;
                float v6 = w[0], v5 = w[1], v4 = w[2], v3 = w[3];
                float v2 = w[4], v1 = w[5], v0 = w[6];
                float t0 = fmaf(A3.x, v0, B3.w);
                float t1 = fmaf(A3.z, v2, A3.y * v1);
                float t2 = fmaf(B3.x, v4, A3.w * v3);
                float t3 = fmaf(B3.z, v6, B3.y * v5);
                ring[wb + 96 + lane] = (t0 + t1) + (t2 + t3);
            }

            // preload group g+1 coefficients (resident since barrier end of
            // g-1 thanks to helper's wait_group 1); off the critical path
            const int st = ((g + 1) & 3) * 4;
            A0 = sc.A[st + 0][lane]; B0 = sc.B[st + 0][lane];
            A1 = sc.A[st + 1][lane]; B1 = sc.B[st + 1][lane];
            A2 = sc.A[st + 2][lane]; B2 = sc.B[st + 2][lane];
            A3 = sc.A[st + 3][lane]; B3 = sc.B[st + 3][lane];
            l0 = sc.I[st + 0][lane];
            l1 = sc.I[st + 1][lane];
            l2 = sc.I[st + 2][lane];
            l3 = sc.I[st + 3][lane];

            __syncthreads();                        // publish group to helper
        }
    } else {
        // ---------------- helper warp ----------------
        float* __restrict__ op = out + b * NN;

        for (int g = 0; g < NGROUP; g++) {
            const int pg = g + 3;                   // group to prefetch
            const int st = (pg & 3) * 4;
#pragma unroll
            for (int k = 0; k < 4; k++)
                prefetch_chunk(&sc, st + k, pg * 4 + k, lane, cA, cB, cI);
            cp_commit();
            cp_wait1();                             // group g+1 resident

            if (g >= 1) {                           // copy group g-1 -> gmem
                const int rb = ((g - 1) & 1) * 128;
                float* o = op + (g - 1) * 128 + lane;
#pragma unroll
                for (int k = 0; k < 4; k++)
                    o[k * 32] = ring[rb + k * 32 + lane];
            }
            __syncthreads();
        }
        // final group's output (compute has exited; its STS were drained by
        // the last __syncthreads)
        {
            const int rb = ((NGROUP - 1) & 1) * 128;
            float* o = op + (NGROUP - 1) * 128 + lane;
#pragma unroll
            for (int k = 0; k < 4; k++)
                o[k * 32] = ring[rb + k * 32 + lane];
        }
    }
}

// ---------------------------------------------------------------------------
// Inputs (metadata order): f0 [B,N] f32, x [B,N] f32, l_b [B,N,2] f32, K int32
// Output: y [B,N] f32
// ---------------------------------------------------------------------------
extern "C" void kernel_launch(void* const* d_in, const int* in_sizes, int n_in,
                              void* d_out, int out_size)
{
    const float* f0 = (const float*)d_in[0];
    const float* x  = (const float*)d_in[1];
    const float* lb = (const float*)d_in[2];
    float* out = (float*)d_out;

    coef_kernel<<<TOTAL / 256, 256>>>(f0, x, lb);
    lpc_kernel<<<BB, 64>>>(out);
}